// round 16
// baseline (speedup 1.0000x reference)
#include <cuda_runtime.h>

typedef unsigned long long u64;

#define LOG2E 1.4426950408889634f
#define LN2   0.6931471805599453f
#define B    512
#define TT   1024
#define L    48
#define RING 16   // emission ring slots (384B each: 48 floats per seq x 2)

__device__ float g_fwd[B];
__device__ float g_gold[B];

static __device__ __forceinline__ u64 pk2(float lo, float hi){ u64 r; asm("mov.b64 %0, {%1, %2};" : "=l"(r) : "f"(lo), "f"(hi)); return r; }
static __device__ __forceinline__ void upk2(u64 v, float& lo, float& hi){ asm("mov.b64 {%0, %1}, %2;" : "=f"(lo), "=f"(hi) : "l"(v)); }
static __device__ __forceinline__ u64 fma2(u64 a, u64 b, u64 c){ u64 d; asm("fma.rn.f32x2 %0, %1, %2, %3;" : "=l"(d) : "l"(a), "l"(b), "l"(c)); return d; }
static __device__ __forceinline__ u64 mul2(u64 a, u64 b){ u64 d; asm("mul.rn.f32x2 %0, %1, %2;" : "=l"(d) : "l"(a), "l"(b)); return d; }
static __device__ __forceinline__ u64 add2(u64 a, u64 b){ u64 d; asm("add.rn.f32x2 %0, %1, %2;" : "=l"(d) : "l"(a), "l"(b)); return d; }
static __device__ __forceinline__ float ex2f(float x){ float y; asm("ex2.approx.ftz.f32 %0, %1;" : "=f"(y) : "f"(x)); return y; }
static __device__ __forceinline__ float lg2f(float x){ float y; asm("lg2.approx.ftz.f32 %0, %1;" : "=f"(y) : "f"(x)); return y; }
static __device__ __forceinline__ unsigned smem_u32(const void* p){
    unsigned a; asm("{ .reg .u64 t; cvta.to.shared.u64 t, %1; cvt.u32.u64 %0, t; }" : "=r"(a) : "l"(p)); return a; }

// Predicated cp.async: guard via setp + @p, no divergent branch.
static __device__ __forceinline__ void cp_async_16_pred(unsigned dst, const float* src, int pred){
    asm volatile(
        "{\n\t"
        ".reg .pred p;\n\t"
        "setp.ne.s32 p, %2, 0;\n\t"
        "@p cp.async.cg.shared.global [%0], [%1], 16;\n\t"
        "}"
        :: "r"(dst), "l"(src), "r"(pred));
}

// ---------------------------------------------------------------------------
// Forward kernel: 256 blocks x 32 threads — TWO sequences per warp.
// Rationale (R15 profile): 0.87 warps/SMSP at issue=37% — single-chain
// latency can't be filled across warps, so fill it WITHIN the warp with a
// second independent chain. et[48] (96 regs) is shared by both chains, so
// the ILP costs only ~30 extra registers.
// Structure per time step (unroll-4 groups, one wait_group 11 per group):
// chain A dot + chain B dot in one basic block (ptxas interleaves), dup-
// layout STS.128 exchange per chain, per-chain ballot masks and pow-2 renorm.
// ---------------------------------------------------------------------------
__global__ __launch_bounds__(32, 1) void crf_fwd_kernel(
    const float* __restrict__ em, const int* __restrict__ mask,
    const float* __restrict__ trans, const float* __restrict__ startt,
    const float* __restrict__ endt)
{
    __shared__ __align__(16) float udup[2][2][128];   // [pingpong][seq][dup state]
    __shared__ __align__(16) float ring[RING * 96];   // [0..47]=A, [48..95]=B per row
    __shared__ unsigned mb[2][32];                    // mask bits per seq

    const int lane = threadIdx.x;
    const int i  = lane < 24 ? lane : 23;             // clamp shadow lanes
    const int bA = blockIdx.x * 2, bB = bA + 1;
    const int j0 = 2 * i, j1 = 2 * i + 1;
    const int isLd = (lane < 24) ? 1 : 0;             // cp.async lane predicate

    // ---- mask bits via ballot (both seqs) ----
    #pragma unroll 1
    for (int k = 0; k < 32; k++) {
        int vA = mask[bA * TT + k * 32 + lane];
        unsigned wA = __ballot_sync(0xFFFFFFFFu, vA != 0);
        if (lane == k) mb[0][k] = wA;
        int vB = mask[bB * TT + k * 32 + lane];
        unsigned wB = __ballot_sync(0xFFFFFFFFu, vB != 0);
        if (lane == k) mb[1][k] = wB;
    }

    // ---- transition columns (j0, j1), exponentiated, packed — SHARED ----
    u64 et[L];
    #pragma unroll
    for (int k = 0; k < L; k++) {
        float e0 = ex2f(trans[k * L + j0] * LOG2E);
        float e1 = ex2f(trans[k * L + j1] * LOG2E);
        et[k] = pk2(e0, e1);
    }
    const float eEnd0 = ex2f(endt[j0] * LOG2E);
    const float eEnd1 = ex2f(endt[j1] * LOG2E);

    // ---- initial states ----
    u64 resA, resB;
    {
        float s0 = startt[j0], s1 = startt[j1];
        float a = ex2f((s0 + em[(size_t)bA * TT * L + j0]) * LOG2E);
        float c = ex2f((s1 + em[(size_t)bA * TT * L + j1]) * LOG2E);
        resA = pk2(a, c);
        float lo, hi; upk2(resA, lo, hi);
        reinterpret_cast<float4*>(&udup[0][0][0])[lane] = make_float4(lo, lo, hi, hi);
        a = ex2f((s0 + em[(size_t)bB * TT * L + j0]) * LOG2E);
        c = ex2f((s1 + em[(size_t)bB * TT * L + j1]) * LOG2E);
        resB = pk2(a, c);
        upk2(resB, lo, hi);
        reinterpret_cast<float4*>(&udup[0][1][0])[lane] = make_float4(lo, lo, hi, hi);
    }

    // ---- cp.async: lanes 0..11 -> seq A, 12..23 -> seq B (16B each) ----
    const float* gsrc = (lane < 12) ? (em + (size_t)bA * TT * L + lane * 4)
                                    : (em + (size_t)bB * TT * L + (lane - 12) * 4);
    const unsigned ring_base = smem_u32(&ring[0]);
    const unsigned dst_off = (lane < 12) ? (unsigned)(lane * 16)
                                         : (unsigned)(192 + (lane - 12) * 16);
    for (int tp = 1; tp < RING; ++tp) {
        cp_async_16_pred(ring_base + (unsigned)tp * 384u + dst_off,
                         gsrc + (size_t)tp * L, isLd);
        asm volatile("cp.async.commit_group;");
    }
    __syncwarp();

    int iAA = 0, iAB = 0;   // exact integer log2 credits per chain

    // One chain's step update. RD_/WR_ = dup-state buffers; RES_ = register
    // state; CR_ = credit accumulator; MBW_ = mask word array row.
    #define CHAIN_STEP(T_, RD_, WR_, RES_, CR_, MBI_, EMOFF_, RN_)             \
    do {                                                                       \
        const int t_ = (T_);                                                   \
        const ulonglong2* rd_ = reinterpret_cast<const ulonglong2*>(RD_);      \
        u64 a0 = 0, a1 = 0, a2 = 0, a3 = 0;                                    \
        u64 first_ = 0;                                                        \
        _Pragma("unroll")                                                      \
        for (int q = 0; q < 12; q++) {                                         \
            ulonglong2 wA_ = rd_[2 * q];                                       \
            ulonglong2 wB_ = rd_[2 * q + 1];                                   \
            if (RN_ && q == 0) first_ = wA_.x;                                 \
            a0 = fma2(wA_.x, et[4 * q + 0], a0);                               \
            a1 = fma2(wA_.y, et[4 * q + 1], a1);                               \
            a2 = fma2(wB_.x, et[4 * q + 2], a2);                               \
            a3 = fma2(wB_.y, et[4 * q + 3], a3);                               \
        }                                                                      \
        u64 dot = add2(add2(a0, a1), add2(a2, a3));                            \
        const int slot_ = t_ & (RING - 1);                                     \
        u64 emp = *reinterpret_cast<const u64*>(&ring[slot_ * 96 + (EMOFF_) + j0]); \
        float emLo_, emHi_; upk2(emp, emLo_, emHi_);                           \
        u64 Ee = pk2(ex2f(emLo_ * LOG2E), ex2f(emHi_ * LOG2E));                \
        u64 prod = mul2(dot, Ee);                                              \
        bool mbit_ = (mb[MBI_][t_ >> 5] >> (t_ & 31)) & 1u;                    \
        u64 sel = mbit_ ? prod : (RES_);                                       \
        if (RN_) {                                                             \
            unsigned eb_ = (unsigned)first_ & 0x7F800000u;                     \
            float f_ = __uint_as_float(0x7F000000u - eb_);                     \
            sel = mul2(sel, pk2(f_, f_));                                      \
            (CR_) += (int)(eb_ >> 23) - 127;                                   \
        }                                                                      \
        (RES_) = sel;                                                          \
        float lo_, hi_; upk2((RES_), lo_, hi_);                                \
        reinterpret_cast<float4*>(WR_)[lane] = make_float4(lo_, lo_, hi_, hi_);\
    } while (0)

    // Full time-step for both chains + single refill/commit + syncwarp.
    #define STEP2(T_, PP_, RN_)                                                \
    do {                                                                       \
        CHAIN_STEP(T_, udup[PP_][0], udup[1 - (PP_)][0], resA, iAA, 0, 0,  RN_);\
        CHAIN_STEP(T_, udup[PP_][1], udup[1 - (PP_)][1], resB, iAB, 1, 48, RN_);\
        int tf_ = (T_) + (RING - 1); if (tf_ > TT - 1) tf_ = TT - 1;           \
        cp_async_16_pred(ring_base + (unsigned)((tf_ & (RING - 1)) * 384)      \
                         + dst_off, gsrc + (size_t)tf_ * L, isLd);             \
        asm volatile("cp.async.commit_group;");                                \
        __syncwarp();                                                          \
    } while (0)

    // Main loop: t = 1..1020 in groups of 4; renorm at t % 4 == 0 (offset 3).
    #pragma unroll 1
    for (int tb = 1; tb + 3 <= TT - 4; tb += 4) {
        asm volatile("cp.async.wait_group 11;");   // rows tb..tb+3 resident
        STEP2(tb,     0, false);
        STEP2(tb + 1, 1, false);
        STEP2(tb + 2, 0, false);
        STEP2(tb + 3, 1, true);
    }
    // Epilogue: t = 1021, 1022, 1023
    asm volatile("cp.async.wait_group 0;");
    STEP2(TT - 3, 0, false);
    STEP2(TT - 2, 1, false);
    STEP2(TT - 1, 0, false);
    #undef STEP2
    #undef CHAIN_STEP

    // ---- finalize both sequences ----
    {
        float lo, hi; upk2(resA, lo, hi);
        float s = (lane < 24) ? (lo * eEnd0 + hi * eEnd1) : 0.f;
        #pragma unroll
        for (int o = 16; o > 0; o >>= 1) s += __shfl_down_sync(0xFFFFFFFFu, s, o);
        if (lane == 0) g_fwd[bA] = (lg2f(s) + (float)iAA) * LN2;
    }
    {
        float lo, hi; upk2(resB, lo, hi);
        float s = (lane < 24) ? (lo * eEnd0 + hi * eEnd1) : 0.f;
        #pragma unroll
        for (int o = 16; o > 0; o >>= 1) s += __shfl_down_sync(0xFFFFFFFFu, s, o);
        if (lane == 0) g_fwd[bB] = (lg2f(s) + (float)iAB) * LN2;
    }
}

// ---------------------------------------------------------------------------
// Gold score kernel: one block per batch element.
// ---------------------------------------------------------------------------
__global__ __launch_bounds__(256, 4) void crf_gold_kernel(
    const float* __restrict__ em, const int* __restrict__ labels,
    const int* __restrict__ mask, const float* __restrict__ trans,
    const float* __restrict__ startt, const float* __restrict__ endt)
{
    __shared__ float red[256];
    __shared__ int   redc[256];
    const int b = blockIdx.x;
    const int tid = threadIdx.x;

    float acc = 0.f;
    int cnt = 0;
    for (int t = tid; t < TT; t += 256) {
        int l = labels[b * TT + t];
        int m = mask[b * TT + t];
        cnt += m;
        float e = em[((size_t)(b * TT) + t) * L + l];
        if (t == 0) {
            acc += startt[l] + e;
        } else {
            int lp = labels[b * TT + t - 1];
            acc += (e + trans[l * L + lp]) * (float)m;
        }
    }
    red[tid] = acc; redc[tid] = cnt;
    __syncthreads();
    for (int s = 128; s > 0; s >>= 1) {
        if (tid < s) { red[tid] += red[tid + s]; redc[tid] += redc[tid + s]; }
        __syncthreads();
    }
    if (tid == 0) {
        int len = redc[0] - 1;
        int last = labels[b * TT + len];
        g_gold[b] = red[0] + endt[last];
    }
}

// ---------------------------------------------------------------------------
// Final reduction: mean(fwd - gold)
// ---------------------------------------------------------------------------
__global__ __launch_bounds__(512, 1) void crf_final_kernel(float* __restrict__ out)
{
    __shared__ float red[512];
    int tid = threadIdx.x;
    red[tid] = g_fwd[tid] - g_gold[tid];
    __syncthreads();
    for (int s = 256; s > 0; s >>= 1) {
        if (tid < s) red[tid] += red[tid + s];
        __syncthreads();
    }
    if (tid == 0) out[0] = red[0] * (1.0f / (float)B);
}

extern "C" void kernel_launch(void* const* d_in, const int* in_sizes, int n_in,
                              void* d_out, int out_size)
{
    const float* em     = (const float*)d_in[0];
    const int*   labels = (const int*)  d_in[1];
    const int*   mask   = (const int*)  d_in[2];
    const float* trans  = (const float*)d_in[3];
    const float* startt = (const float*)d_in[4];
    const float* endt   = (const float*)d_in[5];
    float* out = (float*)d_out;

    crf_fwd_kernel<<<B / 2, 32>>>(em, mask, trans, startt, endt);
    crf_gold_kernel<<<B, 256>>>(em, labels, mask, trans, startt, endt);
    crf_final_kernel<<<1, 512>>>(out);
}

// round 17
// speedup vs baseline: 1.6626x; 1.6626x over previous
#include <cuda_runtime.h>

typedef unsigned long long u64;

#define LOG2E 1.4426950408889634f
#define LN2   0.6931471805599453f
#define B    512
#define TT   1024
#define L    48
#define RING 16   // emission ring slots per warp (192B each)

__device__ float g_fwd[B];
__device__ float g_gold[B];

static __device__ __forceinline__ u64 pk2(float lo, float hi){ u64 r; asm("mov.b64 %0, {%1, %2};" : "=l"(r) : "f"(lo), "f"(hi)); return r; }
static __device__ __forceinline__ void upk2(u64 v, float& lo, float& hi){ asm("mov.b64 {%0, %1}, %2;" : "=f"(lo), "=f"(hi) : "l"(v)); }
static __device__ __forceinline__ u64 fma2(u64 a, u64 b, u64 c){ u64 d; asm("fma.rn.f32x2 %0, %1, %2, %3;" : "=l"(d) : "l"(a), "l"(b), "l"(c)); return d; }
static __device__ __forceinline__ u64 mul2(u64 a, u64 b){ u64 d; asm("mul.rn.f32x2 %0, %1, %2;" : "=l"(d) : "l"(a), "l"(b)); return d; }
static __device__ __forceinline__ u64 add2(u64 a, u64 b){ u64 d; asm("add.rn.f32x2 %0, %1, %2;" : "=l"(d) : "l"(a), "l"(b)); return d; }
static __device__ __forceinline__ float ex2f(float x){ float y; asm("ex2.approx.ftz.f32 %0, %1;" : "=f"(y) : "f"(x)); return y; }
static __device__ __forceinline__ float lg2f(float x){ float y; asm("lg2.approx.ftz.f32 %0, %1;" : "=f"(y) : "f"(x)); return y; }
static __device__ __forceinline__ unsigned smem_u32(const void* p){
    unsigned a; asm("{ .reg .u64 t; cvta.to.shared.u64 t, %1; cvt.u32.u64 %0, t; }" : "=r"(a) : "l"(p)); return a; }

// Predicated cp.async: guard via setp + @p, no divergent branch.
static __device__ __forceinline__ void cp_async_16_pred(unsigned dst, const float* src, int pred){
    asm volatile(
        "{\n\t"
        ".reg .pred p;\n\t"
        "setp.ne.s32 p, %2, 0;\n\t"
        "@p cp.async.cg.shared.global [%0], [%1], 16;\n\t"
        "}"
        :: "r"(dst), "l"(src), "r"(pred));
}

// ---------------------------------------------------------------------------
// Forward kernel: 128 blocks x 128 threads — FOUR fully independent
// single-warp engines per block, one sequence each. Rationale: warp->SMSP is
// wid % 4; R15's single-warp blocks stacked every chain on the same
// scheduler slot (issue stuck at 37% and R16 proved the stall is not
// fillable intra-warp). Here wid 0..3 -> SMSPs 0..3: one chain per
// scheduler, no inter-warp coupling (no __syncthreads on the main path).
// Per-warp engine is byte-identical to the 154.1us R15 kernel: et[48]
// packed in regs, dup-layout STS.128 state exchange, 16-slot cp.async ring,
// unroll-4 groups with one wait_group 11 per group, ballot mask bits,
// exact pow-2 renorm every 4 steps, syncwarp-only.
// ---------------------------------------------------------------------------
__global__ __launch_bounds__(128, 1) void crf_fwd_kernel(
    const float* __restrict__ em, const int* __restrict__ mask,
    const float* __restrict__ trans, const float* __restrict__ startt,
    const float* __restrict__ endt)
{
    __shared__ __align__(16) float udup[4][2][128];     // [warp][pingpong][dup]
    __shared__ __align__(16) float ring[4][RING * 48];  // per-warp ring (3KB each)
    __shared__ unsigned mb[4][32];                      // per-warp mask bits

    const int tid  = threadIdx.x;
    const int w    = tid >> 5;                          // engine / warp id
    const int lane = tid & 31;
    const int i  = lane < 24 ? lane : 23;               // clamp shadow lanes
    const int b  = blockIdx.x * 4 + w;                  // this warp's sequence
    const int j0 = 2 * i, j1 = 2 * i + 1;
    const int isLd = (lane < 12) ? 1 : 0;               // cp.async lane predicate

    // ---- mask bits via ballot ----
    #pragma unroll 1
    for (int k = 0; k < 32; k++) {
        int v = mask[b * TT + k * 32 + lane];
        unsigned wd = __ballot_sync(0xFFFFFFFFu, v != 0);
        if (lane == k) mb[w][k] = wd;
    }

    // ---- transition columns (j0, j1), exponentiated, packed (48 u64) ----
    u64 et[L];
    #pragma unroll
    for (int k = 0; k < L; k++) {
        float e0 = ex2f(trans[k * L + j0] * LOG2E);
        float e1 = ex2f(trans[k * L + j1] * LOG2E);
        et[k] = pk2(e0, e1);
    }
    const float eEnd0 = ex2f(endt[j0] * LOG2E);
    const float eEnd1 = ex2f(endt[j1] * LOG2E);

    // ---- initial state u0 = exp(start + em[0]) ----
    u64 res;
    {
        float a = ex2f((startt[j0] + em[(size_t)b * TT * L + j0]) * LOG2E);
        float c = ex2f((startt[j1] + em[(size_t)b * TT * L + j1]) * LOG2E);
        res = pk2(a, c);
        float lo, hi; upk2(res, lo, hi);
        reinterpret_cast<float4*>(&udup[w][0][0])[lane] = make_float4(lo, lo, hi, hi);
    }

    // ---- cp.async ring prologue: lanes 0..11 copy 16B each (48 floats/row) ----
    const float* gsrc = em + (size_t)b * TT * L + lane * 4;
    const unsigned ring_base = smem_u32(&ring[w][0]);
    const unsigned dst_off = (unsigned)(lane * 16);
    for (int tp = 1; tp < RING; ++tp) {
        cp_async_16_pred(ring_base + (unsigned)tp * 192u + dst_off,
                         gsrc + (size_t)tp * L, isLd);
        asm volatile("cp.async.commit_group;");
    }
    __syncwarp();

    int iA = 0;   // exact integer log2 credit

    // One step: reads RD_ (u[t-1] dup), writes WR_, updates res/iA.
    // RN_ is a compile-time constant — renorm ops exist only where true.
    #define STEP(T_, RD_, WR_, RN_)                                            \
    do {                                                                       \
        const int t_ = (T_);                                                   \
        const ulonglong2* rd_ = reinterpret_cast<const ulonglong2*>(RD_);      \
        u64 a0 = 0, a1 = 0, a2 = 0, a3 = 0;                                    \
        u64 first_ = 0;                                                        \
        _Pragma("unroll")                                                      \
        for (int q = 0; q < 12; q++) {                                         \
            ulonglong2 wA = rd_[2 * q];                                        \
            ulonglong2 wB = rd_[2 * q + 1];                                    \
            if (RN_ && q == 0) first_ = wA.x;                                  \
            a0 = fma2(wA.x, et[4 * q + 0], a0);                                \
            a1 = fma2(wA.y, et[4 * q + 1], a1);                                \
            a2 = fma2(wB.x, et[4 * q + 2], a2);                                \
            a3 = fma2(wB.y, et[4 * q + 3], a3);                                \
        }                                                                      \
        u64 dot = add2(add2(a0, a1), add2(a2, a3));                            \
        const int slot_ = t_ & (RING - 1);                                     \
        u64 emp = *reinterpret_cast<const u64*>(&ring[w][slot_ * 48 + j0]);    \
        float emLo_, emHi_; upk2(emp, emLo_, emHi_);                           \
        u64 Ee = pk2(ex2f(emLo_ * LOG2E), ex2f(emHi_ * LOG2E));                \
        u64 prod = mul2(dot, Ee);                                              \
        bool mbit_ = (mb[w][t_ >> 5] >> (t_ & 31)) & 1u;                       \
        u64 sel = mbit_ ? prod : res;                                          \
        if (RN_) {                                                             \
            unsigned eb_ = (unsigned)first_ & 0x7F800000u;                     \
            float f_ = __uint_as_float(0x7F000000u - eb_);                     \
            sel = mul2(sel, pk2(f_, f_));                                      \
            iA += (int)(eb_ >> 23) - 127;                                      \
        }                                                                      \
        res = sel;                                                             \
        float lo_, hi_; upk2(res, lo_, hi_);                                   \
        reinterpret_cast<float4*>(WR_)[lane] = make_float4(lo_, lo_, hi_, hi_);\
        int tf_ = t_ + (RING - 1); if (tf_ > TT - 1) tf_ = TT - 1;             \
        cp_async_16_pred(ring_base + (unsigned)((tf_ & (RING - 1)) * 192)      \
                         + dst_off, gsrc + (size_t)tf_ * L, isLd);             \
        asm volatile("cp.async.commit_group;");                                \
        __syncwarp();                                                          \
    } while (0)

    // Main loop: t = 1..1020 in groups of 4 (renorm at t % 4 == 0, offset 3).
    #pragma unroll 1
    for (int tb = 1; tb + 3 <= TT - 4; tb += 4) {
        asm volatile("cp.async.wait_group 11;");   // rows tb..tb+3 resident
        STEP(tb,     udup[w][0], udup[w][1], false);
        STEP(tb + 1, udup[w][1], udup[w][0], false);
        STEP(tb + 2, udup[w][0], udup[w][1], false);
        STEP(tb + 3, udup[w][1], udup[w][0], true);
    }
    // Epilogue: t = 1021, 1022, 1023 (all groups already complete)
    asm volatile("cp.async.wait_group 0;");
    STEP(TT - 3, udup[w][0], udup[w][1], false);
    STEP(TT - 2, udup[w][1], udup[w][0], false);
    STEP(TT - 1, udup[w][0], udup[w][1], false);
    #undef STEP

    // ---- finalize: logZ = (log2(sum_j u_j * expEnd_j) + credit) * ln2 ----
    float lo, hi; upk2(res, lo, hi);
    float s = (lane < 24) ? (lo * eEnd0 + hi * eEnd1) : 0.f;
    #pragma unroll
    for (int o = 16; o > 0; o >>= 1) s += __shfl_down_sync(0xFFFFFFFFu, s, o);
    if (lane == 0) g_fwd[b] = (lg2f(s) + (float)iA) * LN2;
}

// ---------------------------------------------------------------------------
// Gold score kernel: one block per batch element.
// ---------------------------------------------------------------------------
__global__ __launch_bounds__(256, 4) void crf_gold_kernel(
    const float* __restrict__ em, const int* __restrict__ labels,
    const int* __restrict__ mask, const float* __restrict__ trans,
    const float* __restrict__ startt, const float* __restrict__ endt)
{
    __shared__ float red[256];
    __shared__ int   redc[256];
    const int b = blockIdx.x;
    const int tid = threadIdx.x;

    float acc = 0.f;
    int cnt = 0;
    for (int t = tid; t < TT; t += 256) {
        int l = labels[b * TT + t];
        int m = mask[b * TT + t];
        cnt += m;
        float e = em[((size_t)(b * TT) + t) * L + l];
        if (t == 0) {
            acc += startt[l] + e;
        } else {
            int lp = labels[b * TT + t - 1];
            acc += (e + trans[l * L + lp]) * (float)m;
        }
    }
    red[tid] = acc; redc[tid] = cnt;
    __syncthreads();
    for (int s = 128; s > 0; s >>= 1) {
        if (tid < s) { red[tid] += red[tid + s]; redc[tid] += redc[tid + s]; }
        __syncthreads();
    }
    if (tid == 0) {
        int len = redc[0] - 1;
        int last = labels[b * TT + len];
        g_gold[b] = red[0] + endt[last];
    }
}

// ---------------------------------------------------------------------------
// Final reduction: mean(fwd - gold)
// ---------------------------------------------------------------------------
__global__ __launch_bounds__(512, 1) void crf_final_kernel(float* __restrict__ out)
{
    __shared__ float red[512];
    int tid = threadIdx.x;
    red[tid] = g_fwd[tid] - g_gold[tid];
    __syncthreads();
    for (int s = 256; s > 0; s >>= 1) {
        if (tid < s) red[tid] += red[tid + s];
        __syncthreads();
    }
    if (tid == 0) out[0] = red[0] * (1.0f / (float)B);
}

extern "C" void kernel_launch(void* const* d_in, const int* in_sizes, int n_in,
                              void* d_out, int out_size)
{
    const float* em     = (const float*)d_in[0];
    const int*   labels = (const int*)  d_in[1];
    const int*   mask   = (const int*)  d_in[2];
    const float* trans  = (const float*)d_in[3];
    const float* startt = (const float*)d_in[4];
    const float* endt   = (const float*)d_in[5];
    float* out = (float*)d_out;

    crf_fwd_kernel<<<B / 4, 128>>>(em, mask, trans, startt, endt);
    crf_gold_kernel<<<B, 256>>>(em, labels, mask, trans, startt, endt);
    crf_final_kernel<<<1, 512>>>(out);
}